// round 17
// baseline (speedup 1.0000x reference)
#include <cuda_runtime.h>
#include <cuda_bf16.h>
#include <math.h>
#include <stdint.h>

#define N_NODES 50000
#define N_EDGES 800000
#define NHEADS 4
#define NEG_SLOPE 0.2f
#define SCAN_BLOCKS 49   // 49 * 1024 = 50176 >= N_NODES

// ---------------- static device scratch (no allocs allowed) ----------------
__device__ __align__(16) float g_feat[N_NODES * 256];   // per-layer linear output [N, H*D]
__device__ __align__(16) float g_x1[N_NODES * 128];     // layer-1 output (fp32, residual use)
__device__ __align__(16) float g_x2[N_NODES * 128];     // layer-2 output
__device__ __align__(16) float g_res3[N_NODES * 256];   // layer-3 residual projection
__device__ __align__(16) float g_el[N_NODES * NHEADS];
__device__ __align__(16) float g_er[N_NODES * NHEADS];
__device__ int   g_cnt[N_NODES];
__device__ int   g_off[N_NODES + 1];
__device__ int   g_cur[N_NODES];
__device__ int   g_csrc[N_EDGES];
__device__ int   g_bsum[SCAN_BLOCKS];
__device__ int   g_bpre[SCAN_BLOCKS];
// bf16 split operands for the tensor-core GEMM
__device__ __align__(16) __nv_bfloat16 g_xhi[N_NODES * 128];
__device__ __align__(16) __nv_bfloat16 g_xlo[N_NODES * 128];
// all weight splits, transposed [m][k]: W1 @0, W2 @16384, W3 @32768, resW3 @65536
__device__ __align__(16) __nv_bfloat16 g_wthi[98304];
__device__ __align__(16) __nv_bfloat16 g_wtlo[98304];

// ================= warp-MMA helpers (baseline sm_80 PTX — no arch-feature
// suffix; tcgen05 is rejected because the harness lowers via compute_103) ====
__device__ __forceinline__ uint32_t cvta_smem(const void* p) {
    uint32_t a;
    asm("{ .reg .u64 t; cvta.to.shared.u64 t, %1; cvt.u32.u64 %0, t; }" : "=r"(a) : "l"(p));
    return a;
}
#define LDSM_X4(R0, R1, R2, R3, ADDR) \
    asm volatile("ldmatrix.sync.aligned.m8n8.x4.shared.b16 {%0,%1,%2,%3}, [%4];" \
                 : "=r"(R0), "=r"(R1), "=r"(R2), "=r"(R3) : "r"(ADDR))
#define MMA_BF16(C, A0, A1, A2, A3, B0, B1) \
    asm volatile("mma.sync.aligned.m16n8k16.row.col.f32.bf16.bf16.f32 " \
                 "{%0,%1,%2,%3},{%4,%5,%6,%7},{%8,%9},{%0,%1,%2,%3};" \
                 : "+f"((C)[0]), "+f"((C)[1]), "+f"((C)[2]), "+f"((C)[3]) \
                 : "r"(A0), "r"(A1), "r"(A2), "r"(A3), "r"(B0), "r"(B1))

// ---------------- CSR build ----------------
__global__ void hist_kernel(const int* __restrict__ dst) {
    int e = blockIdx.x * blockDim.x + threadIdx.x;
    if (e < N_EDGES) atomicAdd(&g_cnt[dst[e]], 1);
}

// parallel scan, stage 1: per-block inclusive scan (49 blocks x 1024)
__global__ void scan_part_kernel() {
    __shared__ int wsum[32];
    int tid = threadIdx.x, lane = tid & 31, wid = tid >> 5;
    int i = blockIdx.x * 1024 + tid;
    int v = (i < N_NODES) ? g_cnt[i] : 0;
    int x = v;
    #pragma unroll
    for (int o = 1; o < 32; o <<= 1) {
        int t = __shfl_up_sync(0xffffffffu, x, o);
        if (lane >= o) x += t;
    }
    if (lane == 31) wsum[wid] = x;
    __syncthreads();
    if (wid == 0) {
        int y = wsum[lane];
        #pragma unroll
        for (int o = 1; o < 32; o <<= 1) {
            int t = __shfl_up_sync(0xffffffffu, y, o);
            if (lane >= o) y += t;
        }
        wsum[lane] = y;
    }
    __syncthreads();
    int incl = x + (wid ? wsum[wid - 1] : 0);
    if (i < N_NODES) g_cur[i] = incl;              // temp: block-local inclusive
    if (tid == 1023) g_bsum[blockIdx.x] = incl;    // block total
}

// stage 2: one warp scans the 49 block sums
__global__ void scan_mid_kernel() {
    int lane = threadIdx.x;
    int carry = 0;
    for (int base = 0; base < SCAN_BLOCKS; base += 32) {
        int v = (base + lane < SCAN_BLOCKS) ? g_bsum[base + lane] : 0;
        int x = v;
        #pragma unroll
        for (int o = 1; o < 32; o <<= 1) {
            int t = __shfl_up_sync(0xffffffffu, x, o);
            if (lane >= o) x += t;
        }
        if (base + lane < SCAN_BLOCKS) g_bpre[base + lane] = carry + x - v;
        carry += __shfl_sync(0xffffffffu, x, 31);
    }
    if (lane == 0) g_off[N_NODES] = carry;
}

// stage 3: compose final exclusive offsets
__global__ void scan_add_kernel() {
    int i = blockIdx.x * blockDim.x + threadIdx.x;
    if (i < N_NODES) {
        int excl = g_bpre[i >> 10] + g_cur[i] - g_cnt[i];
        g_off[i] = excl;
        g_cur[i] = excl;
    }
}

__global__ void scatter_kernel(const int* __restrict__ src, const int* __restrict__ dst) {
    int e = blockIdx.x * blockDim.x + threadIdx.x;
    if (e < N_EDGES) {
        int d = dst[e];
        int p = atomicAdd(&g_cur[d], 1);
        g_csrc[p] = src[e];
    }
}

// ---------------- precision-split converts (also zeroes g_cnt) --------------
__global__ void convert_x_kernel(const float* __restrict__ x) {
    int i = blockIdx.x * blockDim.x + threadIdx.x;
    if (i < N_NODES) g_cnt[i] = 0;
    if (i < N_NODES * 128) {
        float v = x[i];
        __nv_bfloat16 hi = __float2bfloat16(v);
        g_xhi[i] = hi;
        g_xlo[i] = __float2bfloat16(v - __bfloat162float(hi));
    }
}

// all four weight matrices -> transposed bf16 hi/lo in one launch
__global__ void convert_w_all_kernel(const float* __restrict__ W1, const float* __restrict__ W2,
                                     const float* __restrict__ W3, const float* __restrict__ rW3) {
    int i = blockIdx.x * blockDim.x + threadIdx.x;
    if (i >= 98304) return;
    const float* W;
    int M, off;
    if (i < 16384)      { W = W1;  M = 128; off = i; }
    else if (i < 32768) { W = W2;  M = 128; off = i - 16384; }
    else if (i < 65536) { W = W3;  M = 256; off = i - 32768; }
    else                { W = rW3; M = 256; off = i - 65536; }
    int m = off >> 7, k = off & 127;
    float v = W[k * M + m];
    __nv_bfloat16 hi = __float2bfloat16(v);
    g_wthi[i] = hi;
    g_wtlo[i] = __float2bfloat16(v - __bfloat162float(hi));
}

// ---------------- tensor-core GEMM (split-bf16, mma.sync) + el/er epilogue ---
// Layer-3 fusion: when res_out != nullptr, blockIdx.y in 0..3; y<2 computes
// feat (with attention epilogue), y>=2 computes the residual projection into
// res_out (weights for both are contiguous in whi/wlo; same A tile reused).
#define APITCH 136
#define MMA_SMEM_BYTES (4 * 128 * APITCH * 2)

__global__ void __launch_bounds__(256, 1) mma_gemm_kernel(float* __restrict__ out, int M,
        const __nv_bfloat16* __restrict__ whi, const __nv_bfloat16* __restrict__ wlo,
        const float* __restrict__ al, const float* __restrict__ ar, int DA,
        float* __restrict__ res_out) {
    extern __shared__ __nv_bfloat16 sm[];
    __nv_bfloat16* Ahi = sm;
    __nv_bfloat16* Alo = Ahi + 128 * APITCH;
    __nv_bfloat16* Bhi = Alo + 128 * APITCH;
    __nv_bfloat16* Blo = Bhi + 128 * APITCH;
    int tid = threadIdx.x, lane = tid & 31, w = tid >> 5;
    int row0 = blockIdx.x * 128;
    int ycol = blockIdx.y;
    int col0w = ycol * 128;                       // weight row block (into whi/wlo)
    bool resPath = (res_out != nullptr) && (ycol >= 2);
    int col0 = resPath ? (ycol - 2) * 128 : ycol * 128;
    float* dst = resPath ? res_out : out;
    int DAe = resPath ? 0 : DA;

    for (int i = tid; i < 2048; i += 256) {
        int r = i >> 4, c = (i & 15) * 8;
        int gr = row0 + r;
        uint4 vh = make_uint4(0, 0, 0, 0), vl = vh;
        if (gr < N_NODES) {
            vh = *(const uint4*)(g_xhi + gr * 128 + c);
            vl = *(const uint4*)(g_xlo + gr * 128 + c);
        }
        *(uint4*)(Ahi + r * APITCH + c) = vh;
        *(uint4*)(Alo + r * APITCH + c) = vl;
        int gn = col0w + r;
        *(uint4*)(Bhi + r * APITCH + c) = *(const uint4*)(whi + gn * 128 + c);
        *(uint4*)(Blo + r * APITCH + c) = *(const uint4*)(wlo + gn * 128 + c);
    }
    __syncthreads();

    float c[16][4];
    #pragma unroll
    for (int i = 0; i < 16; i++)
        #pragma unroll
        for (int j = 0; j < 4; j++) c[i][j] = 0.f;

    int l7 = lane & 7, mi = lane >> 3;
    int arow = w * 16 + (mi & 1) * 8 + l7;
    int akof = (mi >> 1) * 8;
    uint32_t a_hi_ad = cvta_smem(Ahi) + (uint32_t)(arow * APITCH + akof) * 2;
    uint32_t a_lo_ad = cvta_smem(Alo) + (uint32_t)(arow * APITCH + akof) * 2;
    int bn = (mi >> 1) * 8 + l7;
    int bkof = (mi & 1) * 8;
    uint32_t b_hi_ad = cvta_smem(Bhi) + (uint32_t)(bn * APITCH + bkof) * 2;
    uint32_t b_lo_ad = cvta_smem(Blo) + (uint32_t)(bn * APITCH + bkof) * 2;

    for (int ks = 0; ks < 8; ks++) {
        uint32_t ah0, ah1, ah2, ah3, al0r, al1r, al2r, al3r;
        LDSM_X4(ah0, ah1, ah2, ah3, a_hi_ad + ks * 32);
        LDSM_X4(al0r, al1r, al2r, al3r, a_lo_ad + ks * 32);
        #pragma unroll
        for (int np = 0; np < 8; np++) {
            uint32_t bh0, bh1, bh2, bh3, bl0, bl1, bl2, bl3;
            uint32_t bo = (uint32_t)(np * 16 * APITCH) * 2 + ks * 32;
            LDSM_X4(bh0, bh1, bh2, bh3, b_hi_ad + bo);
            LDSM_X4(bl0, bl1, bl2, bl3, b_lo_ad + bo);
            int nt = 2 * np;
            MMA_BF16(c[nt],     ah0, ah1, ah2, ah3, bh0, bh1);
            MMA_BF16(c[nt],     ah0, ah1, ah2, ah3, bl0, bl1);
            MMA_BF16(c[nt],     al0r, al1r, al2r, al3r, bh0, bh1);
            MMA_BF16(c[nt + 1], ah0, ah1, ah2, ah3, bh2, bh3);
            MMA_BF16(c[nt + 1], ah0, ah1, ah2, ah3, bl2, bl3);
            MMA_BF16(c[nt + 1], al0r, al1r, al2r, al3r, bh2, bh3);
        }
    }

    int t = lane & 3, g2 = lane >> 2;
    int rlo = row0 + w * 16 + g2, rhi = rlo + 8;
    float elL[4] = {0, 0, 0, 0}, erL[4] = {0, 0, 0, 0};
    float elH[4] = {0, 0, 0, 0}, erH[4] = {0, 0, 0, 0};
    #pragma unroll
    for (int nt = 0; nt < 16; nt++) {
        int gc = col0 + nt * 8 + 2 * t;
        if (rlo < N_NODES)
            *(float2*)(dst + rlo * M + gc) = make_float2(c[nt][0], c[nt][1]);
        if (rhi < N_NODES)
            *(float2*)(dst + rhi * M + gc) = make_float2(c[nt][2], c[nt][3]);
        if (DAe) {
            int b = (DAe == 32) ? (nt >> 2) : (nt >> 3);
            float a0v = al[gc], a1v = al[gc + 1];
            float r0v = ar[gc], r1v = ar[gc + 1];
            elL[b] += c[nt][0] * a0v + c[nt][1] * a1v;
            erL[b] += c[nt][0] * r0v + c[nt][1] * r1v;
            elH[b] += c[nt][2] * a0v + c[nt][3] * a1v;
            erH[b] += c[nt][2] * r0v + c[nt][3] * r1v;
        }
    }
    if (DAe) {
        int nb = 128 / DAe;
        #pragma unroll
        for (int b = 0; b < 4; b++) {
            if (b >= nb) break;
            #pragma unroll
            for (int o = 1; o < 4; o <<= 1) {
                elL[b] += __shfl_xor_sync(0xffffffffu, elL[b], o);
                erL[b] += __shfl_xor_sync(0xffffffffu, erL[b], o);
                elH[b] += __shfl_xor_sync(0xffffffffu, elH[b], o);
                erH[b] += __shfl_xor_sync(0xffffffffu, erH[b], o);
            }
            if (t == 0) {
                int h = col0 / DAe + b;
                if (rlo < N_NODES) {
                    g_el[rlo * NHEADS + h] = elL[b];
                    g_er[rlo * NHEADS + h] = erL[b];
                }
                if (rhi < N_NODES) {
                    g_el[rhi * NHEADS + h] = elH[b];
                    g_er[rhi * NHEADS + h] = erH[b];
                }
            }
        }
    }
}

// ---------------- layers 1/2 attention: warp per NODE (M=128) --------------
// No max-pass (|e|~2, exp clamped at 60: softmax identical without the shift).
// Gather loop unrolled x8 -> 8 outstanding LDG.128/warp for latency cover.
__global__ void __launch_bounds__(256) attn_kernel(const float* __restrict__ res,
                                                   float* __restrict__ out) {
    __shared__ int   sh_s[8][32];
    __shared__ float sh_w[8][128];
    int wslot = threadIdx.x >> 5, lane = threadIdx.x & 31;
    int n = blockIdx.x * 8 + wslot;
    if (n >= N_NODES) return;   // uniform per warp
    int beg = g_off[n], end = g_off[n + 1];
    float4 er4 = *(const float4*)(g_er + n * 4);
    float4 den = make_float4(0.f, 0.f, 0.f, 0.f);
    float4 acc0 = make_float4(0.f, 0.f, 0.f, 0.f);
    int myh = lane >> 3;

    for (int j0 = beg; j0 < end; j0 += 32) {
        int j = j0 + lane;
        float4 w4 = make_float4(0.f, 0.f, 0.f, 0.f);
        int s = 0;
        if (j < end) {
            s = g_csrc[j];
            float4 el4 = *(const float4*)(g_el + s * 4);
            float e0 = el4.x + er4.x; e0 = e0 > 0.f ? e0 : NEG_SLOPE * e0;
            float e1 = el4.y + er4.y; e1 = e1 > 0.f ? e1 : NEG_SLOPE * e1;
            float e2 = el4.z + er4.z; e2 = e2 > 0.f ? e2 : NEG_SLOPE * e2;
            float e3 = el4.w + er4.w; e3 = e3 > 0.f ? e3 : NEG_SLOPE * e3;
            w4.x = __expf(fminf(e0, 60.f));
            w4.y = __expf(fminf(e1, 60.f));
            w4.z = __expf(fminf(e2, 60.f));
            w4.w = __expf(fminf(e3, 60.f));
            den.x += w4.x; den.y += w4.y; den.z += w4.z; den.w += w4.w;
        }
        sh_s[wslot][lane] = s;
        *(float4*)&sh_w[wslot][lane * 4] = w4;
        __syncwarp();
        int cnt = min(32, end - j0);
        #pragma unroll 8
        for (int t = 0; t < cnt; t++) {
            int st = sh_s[wslot][t];
            float wt = sh_w[wslot][t * 4 + myh];
            const float* fp = g_feat + st * 128;
            float4 f = *(const float4*)(fp + lane * 4);
            acc0.x = fmaf(wt, f.x, acc0.x);
            acc0.y = fmaf(wt, f.y, acc0.y);
            acc0.z = fmaf(wt, f.z, acc0.z);
            acc0.w = fmaf(wt, f.w, acc0.w);
        }
        __syncwarp();
    }

    #pragma unroll
    for (int o = 16; o; o >>= 1) {
        den.x += __shfl_xor_sync(0xffffffffu, den.x, o);
        den.y += __shfl_xor_sync(0xffffffffu, den.y, o);
        den.z += __shfl_xor_sync(0xffffffffu, den.z, o);
        den.w += __shfl_xor_sync(0xffffffffu, den.w, o);
    }
    bool ne = end > beg;

    float a = (lane & 8) ? den.y : den.x;
    float b = (lane & 8) ? den.w : den.z;
    float dv = (lane & 16) ? b : a;
    float inv = ne ? 1.f / dv : 0.f;
    float4 r = *(const float4*)(res + n * 128 + lane * 4);
    float4 v;
    v.x = fmaxf(fmaf(acc0.x, inv, r.x), 0.f);
    v.y = fmaxf(fmaf(acc0.y, inv, r.y), 0.f);
    v.z = fmaxf(fmaf(acc0.z, inv, r.z), 0.f);
    v.w = fmaxf(fmaf(acc0.w, inv, r.w), 0.f);
    *(float4*)(out + n * 128 + lane * 4) = v;
    // emit next layer's bf16 split input
    __nv_bfloat16 hx = __float2bfloat16(v.x), hy = __float2bfloat16(v.y);
    __nv_bfloat16 hz = __float2bfloat16(v.z), hw = __float2bfloat16(v.w);
    __nv_bfloat162 hA; hA.x = hx; hA.y = hy;
    __nv_bfloat162 hB; hB.x = hz; hB.y = hw;
    *(__nv_bfloat162*)(g_xhi + n * 128 + lane * 4) = hA;
    *(__nv_bfloat162*)(g_xhi + n * 128 + lane * 4 + 2) = hB;
    __nv_bfloat162 lA, lB;
    lA.x = __float2bfloat16(v.x - __bfloat162float(hx));
    lA.y = __float2bfloat16(v.y - __bfloat162float(hy));
    lB.x = __float2bfloat16(v.z - __bfloat162float(hz));
    lB.y = __float2bfloat16(v.w - __bfloat162float(hw));
    *(__nv_bfloat162*)(g_xlo + n * 128 + lane * 4) = lA;
    *(__nv_bfloat162*)(g_xlo + n * 128 + lane * 4 + 2) = lB;
}

// ---------------- layer-3 attention: TWO warps per node (M=256) -------------
// Warp pair (wslot 2i, 2i+1) = node halves; each warp owns 128 cols = 2 heads,
// one float4 LDG per edge (unroll 8 -> 8 in flight). Mean-over-heads combined
// cross-warp through smem (half-1 deposits its head-pair sum; half-0 writes).
// N_NODES % 4 == 0 so every block carries exactly 4 full nodes.
__global__ void __launch_bounds__(256) attn3_kernel(const float* __restrict__ res,
                                                    float* __restrict__ out) {
    __shared__ int   sh_s[8][32];
    __shared__ float sh_w[8][64];
    __shared__ float sh_m[4][64];
    int wslot = threadIdx.x >> 5, lane = threadIdx.x & 31;
    int gw = blockIdx.x * 8 + wslot;
    int n = gw >> 1, half = gw & 1;
    bool active = n < N_NODES;
    int beg = 0, end = 0;
    float2 er2 = make_float2(0.f, 0.f);
    if (active) {
        beg = g_off[n];
        end = g_off[n + 1];
        er2 = *(const float2*)(g_er + n * 4 + half * 2);
    }
    float2 den = make_float2(0.f, 0.f);
    float4 acc = make_float4(0.f, 0.f, 0.f, 0.f);
    int h01 = lane >> 4;   // which of this half's two heads my columns belong to

    for (int j0 = beg; j0 < end; j0 += 32) {
        int j = j0 + lane;
        float2 w2 = make_float2(0.f, 0.f);
        int s = 0;
        if (j < end) {
            s = g_csrc[j];
            float2 el2 = *(const float2*)(g_el + s * 4 + half * 2);
            float e0 = el2.x + er2.x; e0 = e0 > 0.f ? e0 : NEG_SLOPE * e0;
            float e1 = el2.y + er2.y; e1 = e1 > 0.f ? e1 : NEG_SLOPE * e1;
            w2.x = __expf(fminf(e0, 60.f));
            w2.y = __expf(fminf(e1, 60.f));
            den.x += w2.x;
            den.y += w2.y;
        }
        sh_s[wslot][lane] = s;
        *(float2*)&sh_w[wslot][lane * 2] = w2;
        __syncwarp();
        int cnt = min(32, end - j0);
        #pragma unroll 8
        for (int t = 0; t < cnt; t++) {
            int st = sh_s[wslot][t];
            float wt = sh_w[wslot][t * 2 + h01];
            const float* fp = g_feat + st * 256 + half * 128;
            float4 f = *(const float4*)(fp + lane * 4);
            acc.x = fmaf(wt, f.x, acc.x);
            acc.y = fmaf(wt, f.y, acc.y);
            acc.z = fmaf(wt, f.z, acc.z);
            acc.w = fmaf(wt, f.w, acc.w);
        }
        __syncwarp();
    }

    #pragma unroll
    for (int o = 16; o; o >>= 1) {
        den.x += __shfl_xor_sync(0xffffffffu, den.x, o);
        den.y += __shfl_xor_sync(0xffffffffu, den.y, o);
    }
    bool ne = end > beg;
    float dv = (lane & 16) ? den.y : den.x;
    float inv = ne ? 1.f / dv : 0.f;

    float4 v = make_float4(0.f, 0.f, 0.f, 0.f);
    if (active) {
        float4 r = *(const float4*)(res + n * 256 + half * 128 + lane * 4);
        v.x = fmaf(acc.x, inv, r.x);
        v.y = fmaf(acc.y, inv, r.y);
        v.z = fmaf(acc.z, inv, r.z);
        v.w = fmaf(acc.w, inv, r.w);
    }
    // sum this half's two heads: lane l (<16) pairs with l+16 at same d
    v.x += __shfl_xor_sync(0xffffffffu, v.x, 16);
    v.y += __shfl_xor_sync(0xffffffffu, v.y, 16);
    v.z += __shfl_xor_sync(0xffffffffu, v.z, 16);
    v.w += __shfl_xor_sync(0xffffffffu, v.w, 16);

    if (half == 1 && lane < 16)
        *(float4*)&sh_m[wslot >> 1][lane * 4] = v;
    __syncthreads();
    if (half == 0 && lane < 16 && active) {
        float4 o2 = *(float4*)&sh_m[wslot >> 1][lane * 4];
        float4 tot;
        tot.x = 0.25f * (v.x + o2.x);
        tot.y = 0.25f * (v.y + o2.y);
        tot.z = 0.25f * (v.z + o2.z);
        tot.w = 0.25f * (v.w + o2.w);
        *(float4*)(out + n * 64 + lane * 4) = tot;
    }
}

// ---------------- launch ----------------
// NOTE: device buffers passed as kernel args from host MUST come from
// cudaGetSymbolAddress (host symbol decay = host shadow address; on GB300 ATS
// the GPU silently writes host RAM). Device-side references to globals are fine.
#define GRID_ROWS ((N_NODES + 127) / 128)
#define ATTN_GRID ((N_NODES + 7) / 8)
#define ATTN3_GRID ((N_NODES * 2 + 7) / 8)

extern "C" void kernel_launch(void* const* d_in, const int* in_sizes, int n_in,
                              void* d_out, int out_size) {
    const float* h     = (const float*)d_in[0];
    const float* W1    = (const float*)d_in[1];
    const float* al1   = (const float*)d_in[2];
    const float* ar1   = (const float*)d_in[3];
    const float* W2    = (const float*)d_in[4];
    const float* al2   = (const float*)d_in[5];
    const float* ar2   = (const float*)d_in[6];
    const float* W3    = (const float*)d_in[7];
    const float* al3   = (const float*)d_in[8];
    const float* ar3   = (const float*)d_in[9];
    const float* resW3 = (const float*)d_in[10];
    const int*   src   = (const int*)d_in[11];
    const int*   dst   = (const int*)d_in[12];
    float* out = (float*)d_out;

    float* g_feat_p; cudaGetSymbolAddress((void**)&g_feat_p, g_feat);
    float* g_x1_p;   cudaGetSymbolAddress((void**)&g_x1_p, g_x1);
    float* g_x2_p;   cudaGetSymbolAddress((void**)&g_x2_p, g_x2);
    float* g_res3_p; cudaGetSymbolAddress((void**)&g_res3_p, g_res3);
    __nv_bfloat16* whi; cudaGetSymbolAddress((void**)&whi, g_wthi);
    __nv_bfloat16* wlo; cudaGetSymbolAddress((void**)&wlo, g_wtlo);

    cudaFuncSetAttribute(mma_gemm_kernel, cudaFuncAttributeMaxDynamicSharedMemorySize,
                         MMA_SMEM_BYTES);

    // converts (also zeroes g_cnt) + CSR build (3-stage parallel scan)
    convert_x_kernel<<<(N_NODES * 128 + 255) / 256, 256>>>(h);
    convert_w_all_kernel<<<(98304 + 255) / 256, 256>>>(W1, W2, W3, resW3);
    hist_kernel<<<(N_EDGES + 255) / 256, 256>>>(dst);
    scan_part_kernel<<<SCAN_BLOCKS, 1024>>>();
    scan_mid_kernel<<<1, 32>>>();
    scan_add_kernel<<<(N_NODES + 255) / 256, 256>>>();
    scatter_kernel<<<(N_EDGES + 255) / 256, 256>>>(src, dst);

    // ---- Layer 1: 128 -> 4x32, residual = h, relu; attn emits bf16 x1
    mma_gemm_kernel<<<dim3(GRID_ROWS, 1), 256, MMA_SMEM_BYTES>>>(
        g_feat_p, 128, whi, wlo, al1, ar1, 32, nullptr);
    attn_kernel<<<ATTN_GRID, 256>>>(h, g_x1_p);

    // ---- Layer 2: 128 -> 4x32, residual = x1, relu; attn emits bf16 x2
    mma_gemm_kernel<<<dim3(GRID_ROWS, 1), 256, MMA_SMEM_BYTES>>>(
        g_feat_p, 128, whi + 16384, wlo + 16384, al2, ar2, 32, nullptr);
    attn_kernel<<<ATTN_GRID, 256>>>(g_x1_p, g_x2_p);

    // ---- Layer 3 fused: feat = x2@W3 (y=0,1 with el/er epilogue) AND
    //      res3 = x2@resW3 (y=2,3), same A tile, contiguous weights
    mma_gemm_kernel<<<dim3(GRID_ROWS, 4), 256, MMA_SMEM_BYTES>>>(
        g_feat_p, 256, whi + 32768, wlo + 32768, al3, ar3, 64, g_res3_p);
    attn3_kernel<<<ATTN3_GRID, 256>>>(g_res3_p, out);
}